// round 2
// baseline (speedup 1.0000x reference)
#include <cuda_runtime.h>
#include <math.h>

#define Bb 64
#define Ss 256
#define Ww 32
#define Tt 32

__device__ float g_num[Bb];
__device__ float g_den[Bb];

#define K_SENT (-(1<<30))

// ---- shared memory layout (one static buffer, role-dependent) ----
// denominator role:
#define D_A    0        // float[32][32]  exp-domain alpha ring
#define D_P    4096     // float[32][36]  transposed partials P[t][d]
#define D_K    8704     // int[32]        per-slot exponent K
#define D_R    8832     // int            current reference exponent R
#define D_LEN  8836     // int
// numerator role:
#define N_TAGS  0       // int[256][33]
#define N_TRANS 33792   // float[32][33]
#define N_START 38016   // float[32]
#define N_END   38144   // float[32]
#define N_MROW  38272   // int[256]
#define N_WRED  39296   // float[32]
#define N_LEN   39424   // int
#define SMEM_BYTES 40960

__global__ void __launch_bounds__(1024, 1)
crf_main(const float* __restrict__ logits,
         const int*   __restrict__ tags,
         const int*   __restrict__ mask,
         const float* __restrict__ trans,
         const float* __restrict__ start_tr,
         const float* __restrict__ end_tr)
{
    __shared__ __align__(16) char sm[SMEM_BYTES];
    const int tid  = threadIdx.x;
    const int warp = tid >> 5;
    const int lane = tid & 31;

    if (blockIdx.x < Bb) {
        // ================= DENOMINATOR: forward algorithm, one CTA per batch =================
        const int b = blockIdx.x;
        float* A     = (float*)(sm + D_A);
        float* P     = (float*)(sm + D_P);
        int*   Kring = (int*)  (sm + D_K);
        int*   Rsh   = (int*)  (sm + D_R);
        int*   lensh = (int*)  (sm + D_LEN);

        // E column for this thread's tag t=lane: e[t2] = exp(trans[t2][t])
        float e[32];
        #pragma unroll
        for (int k = 0; k < 32; k++) e[k] = __expf(trans[k * Tt + lane]);
        const float es = __expf(start_tr[lane]);

        A[warp * 32 + lane] = 0.f;
        if (tid < 32) Kring[tid] = K_SENT;
        if (tid == 0) *Rsh = 0;
        if (warp == 0) {
            int s = 0;
            #pragma unroll
            for (int k = 0; k < 8; k++) s += mask[b * Ss + lane + 32 * k];
            #pragma unroll
            for (int o = 16; o; o >>= 1) s += __shfl_xor_sync(0xffffffffu, s, o);
            if (lane == 0) *lensh = s;
        }
        __syncthreads();
        const int len = *lensh;

        int R = 0;            // reference exponent for current step (all warps)
        int myK = K_SENT;     // warp0 only: lane s holds K of ring slot s

        const int d = warp;   // this warp's duration lag
        const float* lp = logits + (size_t)b * Ss * Ww * Tt + d * Tt + lane;
        float nxt = lp[0];

        for (int j = 0; j < len; j++) {
            float cur = nxt;
            if (j + 1 < len) nxt = lp[(size_t)(j + 1) * (Ww * Tt)];
            float em = __expf(cur);

            float p;
            if (d < j) {
                int slot = (j - 1 - d) & 31;
                int diff = Kring[slot] - R;                 // <= 0 by construction
                float f = (diff < -126) ? 0.f : __int_as_float((127 + diff) << 23);
                const float4* Ar = (const float4*)(A + slot * 32);
                float acc = 0.f;
                #pragma unroll
                for (int g = 0; g < 8; g++) {
                    float4 v = Ar[g];                       // broadcast LDS.128
                    acc = fmaf(v.x, e[4*g+0], acc);
                    acc = fmaf(v.y, e[4*g+1], acc);
                    acc = fmaf(v.z, e[4*g+2], acc);
                    acc = fmaf(v.w, e[4*g+3], acc);
                }
                p = acc * (em * f);
            } else if (d == j) {
                float f = (R > 126) ? 0.f : __int_as_float((127 - R) << 23);
                p = es * (em * f);
            } else {
                p = 0.f;
            }
            P[lane * 36 + d] = p;                           // transposed, conflict-free
            __syncthreads();

            if (warp == 0) {
                const float4* Pr = (const float4*)(P + lane * 36);
                float4 s = Pr[0];
                #pragma unroll
                for (int g = 1; g < 8; g++) {
                    float4 q = Pr[g];
                    s.x += q.x; s.y += q.y; s.z += q.z; s.w += q.w;
                }
                float out = (s.x + s.y) + (s.z + s.w);      // alpha_j[t=lane], scale 2^R
                float mv = out;
                #pragma unroll
                for (int o = 16; o; o >>= 1) mv = fmaxf(mv, __shfl_xor_sync(0xffffffffu, mv, o));
                int ee = ((__float_as_int(mv) >> 23) & 255) - 127;   // exponent of max
                float scale = __int_as_float((127 - ee) << 23);      // exact 2^-ee
                int slotn = j & 31;
                A[slotn * 32 + lane] = out * scale;
                int Kn = R + ee;
                if (lane == slotn) myK = Kn;
                if (lane == 0) Kring[slotn] = Kn;
                // reference exponent for step j+1
                int rm = myK;
                #pragma unroll
                for (int o = 16; o; o >>= 1) rm = max(rm, __shfl_xor_sync(0xffffffffu, rm, o));
                if (j + 1 < Ww) rm = max(rm, 0);            // start path still alive
                R = rm;
                if (lane == 0) *Rsh = R;
            }
            __syncthreads();
            if (warp != 0) R = *Rsh;
        }

        if (warp == 0) {
            int slot = (len - 1) & 31;
            float v = A[slot * 32 + lane] * __expf(end_tr[lane]);
            #pragma unroll
            for (int o = 16; o; o >>= 1) v += __shfl_xor_sync(0xffffffffu, v, o);
            int Kl = __shfl_sync(0xffffffffu, myK, slot);
            if (lane == 0)
                g_den[b] = (float)(log((double)v) + (double)Kl * 0.6931471805599453);
        }
    } else {
        // ================= NUMERATOR: joint likelihood, one CTA per batch =================
        const int b = blockIdx.x - Bb;
        int*   tags_s  = (int*)  (sm + N_TAGS);
        float* trans_s = (float*)(sm + N_TRANS);
        float* start_s = (float*)(sm + N_START);
        float* end_s   = (float*)(sm + N_END);
        int*   mrow    = (int*)  (sm + N_MROW);
        float* wred    = (float*)(sm + N_WRED);
        int*   lensh   = (int*)  (sm + N_LEN);

        for (int i = tid; i < Ss * Ww; i += 1024) {
            int j = i >> 5, w = i & 31;
            tags_s[j * 33 + w] = tags[(size_t)b * Ss * Ww + i];
        }
        if (tid < Tt * Tt) {
            int r = tid >> 5, c = tid & 31;
            trans_s[r * 33 + c] = trans[tid];
        }
        if (tid < 32) { start_s[tid] = start_tr[tid]; end_s[tid] = end_tr[tid]; }
        for (int i = tid; i < Ss; i += 1024) mrow[i] = mask[b * Ss + i];
        __syncthreads();
        if (tid < 32) {
            int s = 0;
            #pragma unroll
            for (int k = 0; k < 8; k++) s += mrow[tid + 32 * k];
            #pragma unroll
            for (int o = 16; o; o >>= 1) s += __shfl_xor_sync(0xffffffffu, s, o);
            if (tid == 0) *lensh = s;
        }
        __syncthreads();
        const int len = *lensh;

        float acc = 0.f;
        #pragma unroll 1
        for (int it = 0; it < 8; it++) {
            int j  = warp + 32 * it;
            int tm = mrow[j];
            int dd = lane;
            int tag = tags_s[j * 33 + dd];
            float contrib = 0.f;
            if (tm && dd <= j) {
                float ts;
                if (dd == j) {
                    ts = start_s[tag];
                } else {
                    ts = 0.f;
                    const int* prow = tags_s + (j - dd - 1) * 33;
                    #pragma unroll
                    for (int w2 = 0; w2 < 32; w2++) {
                        int pt = prow[w2];
                        float tv = trans_s[pt * 33 + tag];
                        if (pt != 0) ts += tv;
                    }
                }
                float emv = 0.f;
                if (tag != 0)
                    emv = logits[(((size_t)b * Ss + j) * Ww + dd) * Tt + tag];
                contrib = ts + emv;
            }
            acc += contrib;
        }
        #pragma unroll
        for (int o = 16; o; o >>= 1) acc += __shfl_xor_sync(0xffffffffu, acc, o);
        if (lane == 0) wred[warp] = acc;
        __syncthreads();
        if (warp == 0) {
            float s = wred[lane];
            int li = len - 1;
            int lt = tags_s[li * 33 + lane];
            if (lt != 0) s += end_s[lt];
            #pragma unroll
            for (int o = 16; o; o >>= 1) s += __shfl_xor_sync(0xffffffffu, s, o);
            if (lane == 0) g_num[b] = s;
        }
    }
}

__global__ void crf_finalize(float* __restrict__ out, int out_size)
{
    __shared__ float sh[2];
    int t = threadIdx.x;   // 64 threads
    float n = g_num[t];
    float d = g_den[t];
    if (1 + t < out_size) out[1 + t] = n;
    float diff = n - d;
    #pragma unroll
    for (int o = 16; o; o >>= 1) diff += __shfl_xor_sync(0xffffffffu, diff, o);
    if ((t & 31) == 0) sh[t >> 5] = diff;
    __syncthreads();
    if (t == 0 && out_size > 0) out[0] = (sh[0] + sh[1]) * (1.0f / 64.0f);
}

extern "C" void kernel_launch(void* const* d_in, const int* in_sizes, int n_in,
                              void* d_out, int out_size)
{
    const float* logits   = (const float*)d_in[0];
    const int*   tags     = (const int*)  d_in[1];
    const int*   mask     = (const int*)  d_in[2];
    const float* trans    = (const float*)d_in[3];
    const float* start_tr = (const float*)d_in[4];
    const float* end_tr   = (const float*)d_in[5];

    crf_main<<<2 * Bb, 1024>>>(logits, tags, mask, trans, start_tr, end_tr);
    crf_finalize<<<1, 64>>>((float*)d_out, out_size);
}